// round 1
// baseline (speedup 1.0000x reference)
#include <cuda_runtime.h>
#include <cstdint>

// ---------------------------------------------------------------------------
// Problem constants (fixed shapes per reference)
// ---------------------------------------------------------------------------
#define NB    32
#define IMGW  224
#define HPIX  (IMGW*IMGW)        // 50176
#define NRr   400                // radius samples
#define NAa   1024               // azimuth samples
#define ED    96                 // embed dim
#define KDIM  1200               // 3 * 25 * 16 folded patch size
#define MDIM  (NB*16*64)         // 32768 output patches
#define PI_F  3.14159265358979323846f

// Scratch (device globals; no runtime allocation allowed)
__device__ float g_S[(size_t)MDIM * KDIM];   // sampled, patch-major [M][K]
__device__ float g_w2r[20*96*96];            // w2 reordered [ij][c1][c2]
__device__ float g_Wt[KDIM*ED];              // folded weight [k][c2]
__device__ float g_beff[ED];                 // folded bias

// ---------------------------------------------------------------------------
// f32x2 packed-FMA helpers (sm_103a FFMA2 — only reachable via PTX)
// ---------------------------------------------------------------------------
__device__ __forceinline__ unsigned long long pk2(float lo, float hi) {
    unsigned long long r;
    asm("mov.b64 %0, {%1,%2};" : "=l"(r) : "f"(lo), "f"(hi));
    return r;
}
__device__ __forceinline__ void upk2(unsigned long long v, float& lo, float& hi) {
    asm("mov.b64 {%0,%1}, %2;" : "=f"(lo), "=f"(hi) : "l"(v));
}
__device__ __forceinline__ void fma2(unsigned long long& d,
                                     unsigned long long a, unsigned long long b) {
    asm("fma.rn.f32x2 %0, %1, %2, %0;" : "+l"(d) : "l"(a), "l"(b));
}

// ---------------------------------------------------------------------------
// Prep 1: reorder w2 [c2][c1][i][j] -> w2r [ij][c1][c2]  (coalesced reads later)
// ---------------------------------------------------------------------------
__global__ void w2r_kernel(const float* __restrict__ w2, float* __restrict__ w2r) {
    int idx = blockIdx.x * blockDim.x + threadIdx.x;
    if (idx >= 20*96*96) return;
    int ij  = idx / (96*96);
    int rem = idx - ij*96*96;
    int c1  = rem / 96;
    int c2  = rem - c1*96;
    int i = ij >> 2, j = ij & 3;
    w2r[idx] = w2[((c2*96 + c1)*5 + i)*4 + j];
}

// ---------------------------------------------------------------------------
// Prep 2: fold conv1∘conv2 weights:
//   Wt[k][c2] = sum_c1 w2[c2,c1,i,j] * w1[c1,c,p,q]
//   k = c*400 + r*16 + a,  r = i*5+p (0..24),  a = j*4+q (0..15)
// ---------------------------------------------------------------------------
__global__ void weff_kernel(const float* __restrict__ w1,
                            const float* __restrict__ w2r,
                            float* __restrict__ Wt) {
    int k  = blockIdx.x;        // 0..1199
    int c2 = threadIdx.x;       // 0..95
    int c   = k / 400;
    int rem = k - c*400;
    int r = rem >> 4;
    int a = rem & 15;
    int i = r / 5, p = r - i*5;
    int j = a >> 2, q = a & 3;

    __shared__ float w1col[96];
    w1col[c2] = w1[((c2*3 + c)*5 + p)*4 + q];
    __syncthreads();

    const float* wp = w2r + (i*4 + j)*96*96 + c2;
    float s = 0.f;
#pragma unroll 8
    for (int c1 = 0; c1 < 96; c1++) s += w1col[c1] * wp[c1*96];
    Wt[k*96 + c2] = s;
}

// ---------------------------------------------------------------------------
// Prep 3: folded bias + theta_max output
//   beff[c2] = b2[c2] + sum_c1 b1[c1] * sum_ij w2[c2,c1,i,j]
// ---------------------------------------------------------------------------
__global__ void prep_kernel(const float* __restrict__ b1, const float* __restrict__ b2,
                            const float* __restrict__ w2r, float* __restrict__ beff,
                            float* __restrict__ outTheta, int nTheta) {
    int c2 = threadIdx.x;   // blockDim = 96
    float s = b2[c2];
    for (int c1 = 0; c1 < 96; c1++) {
        float t = 0.f;
#pragma unroll
        for (int ij = 0; ij < 20; ij++) t += w2r[ij*9216 + c1*96 + c2];
        s += b1[c1] * t;
    }
    beff[c2] = s;
    if (c2 < nTheta) outTheta[c2] = 1.5707963267948966f;   // pi/2
}

// ---------------------------------------------------------------------------
// Sampling: polar grid + bilinear gather, written patch-major into S[M][K]
// thread = (b, ir, ia), consecutive lanes = consecutive azimuth (arc locality)
// ---------------------------------------------------------------------------
__global__ __launch_bounds__(256) void sample_kernel(const float* __restrict__ x,
                                                     const float* __restrict__ dist,
                                                     float* __restrict__ S) {
    int t = blockIdx.x * blockDim.x + threadIdx.x;   // exactly 32*400*1024 threads
    int ia = t & 1023;
    int ir = (t >> 10) % 400;
    int b  = t / (400*1024);

    const float* dp = dist + b*4;
    float c0 = 0.2f + dp[0], c1 = 0.2f + dp[1];
    float c2 = 0.2f + dp[2], c3 = 0.2f + dp[3];

    const float tm = PI_F * 0.5f;
    float th  = tm * (ir + 0.5f) * (1.0f/400.0f);
    float t2  = th*th;
    float pn  = th * (c0 + t2*(c1 + t2*(c2 + t2*c3)));
    float tm2 = tm*tm;
    float pd  = tm * (c0 + tm2*(c1 + tm2*(c2 + tm2*c3)));
    float r   = pn / pd * (IMGW * 0.5f);             // < 112

    float phi = 2.0f*PI_F * (ia + 0.5f) * (1.0f/1024.0f);
    float sp, cp;
    __sincosf(phi, &sp, &cp);
    float xc = r*cp, yc = r*sp;

    // reference: grid = [yc/(W/2), xc/(H/2)]; grid[...,0] is the x (width) coord
    float gx = (yc * (1.0f/112.0f) + 1.0f) * 0.5f * (IMGW - 1);
    float gy = (xc * (1.0f/112.0f) + 1.0f) * 0.5f * (IMGW - 1);

    float x0f = floorf(gx), y0f = floorf(gy);
    float wx1 = gx - x0f, wx0 = 1.0f - wx1;
    float wy1 = gy - y0f, wy0 = 1.0f - wy1;
    int x0 = min(222, max(0, (int)x0f));
    int y0 = min(222, max(0, (int)y0f));

    float w00 = wx0*wy0, w01 = wx1*wy0, w10 = wx0*wy1, w11 = wx1*wy1;

    const float* base = x + (size_t)b*3*HPIX + y0*IMGW + x0;
    int patch = b*1024 + (ir/25)*64 + (ia >> 4);
    float* so = S + (size_t)patch*KDIM + (ir % 25)*16 + (ia & 15);

#pragma unroll
    for (int ch = 0; ch < 3; ch++) {
        const float* p = base + ch*HPIX;
        float v = w00*__ldg(p)        + w01*__ldg(p + 1)
                + w10*__ldg(p + IMGW) + w11*__ldg(p + IMGW + 1);
        so[ch*400] = v;
    }
}

// ---------------------------------------------------------------------------
// GEMM: C[M=32768][96] = S[M][1200] @ Wt[1200][96] + beff
// BM=128, BN=96, BK=8, 256 threads, 8x6 micro-tile per thread, f32x2 FMAs
// ---------------------------------------------------------------------------
__global__ __launch_bounds__(256, 2)
void gemm_kernel(const float* __restrict__ A, const float* __restrict__ Bw,
                 const float* __restrict__ bias, float* __restrict__ C) {
    __shared__ float As[8][128];   // transposed: [k][m]
    __shared__ float Bs[8*96];     // flat [k*96 + n] == contiguous 768 of Bw

    int tid = threadIdx.x;
    int m0  = blockIdx.x * 128;
    int tx  = tid & 15;            // col group: cols tx*6 .. tx*6+5
    int ty  = tid >> 4;            // row group: rows ty*8 .. ty*8+7
    int lm  = tid >> 1;            // A-loader row 0..127
    int lk  = (tid & 1) * 4;       // A-loader k offset 0 or 4

    const float* Ap = A + (size_t)(m0 + lm)*KDIM + lk;

    // prologue loads
    float4 ra = *(const float4*)Ap;
    float rb[3];
#pragma unroll
    for (int r = 0; r < 3; r++) rb[r] = Bw[tid + 256*r];

    unsigned long long acc[4][6];
#pragma unroll
    for (int r = 0; r < 4; r++)
#pragma unroll
        for (int j = 0; j < 6; j++) acc[r][j] = 0ULL;

    const int NKT = KDIM / 8;   // 150
    for (int kt = 0; kt < NKT; ++kt) {
        __syncthreads();
        As[lk+0][lm] = ra.x; As[lk+1][lm] = ra.y;
        As[lk+2][lm] = ra.z; As[lk+3][lm] = ra.w;
#pragma unroll
        for (int r = 0; r < 3; r++) Bs[tid + 256*r] = rb[r];
        __syncthreads();

        if (kt + 1 < NKT) {   // prefetch next tile into registers
            ra = *(const float4*)(Ap + (kt+1)*8);
            const float* bp = Bw + (size_t)(kt+1)*768;
#pragma unroll
            for (int r = 0; r < 3; r++) rb[r] = bp[tid + 256*r];
        }

#pragma unroll
        for (int k = 0; k < 8; k++) {
            float4 a0 = *(const float4*)&As[k][ty*8];
            float4 a1 = *(const float4*)&As[k][ty*8 + 4];
            unsigned long long ap[4] = { pk2(a0.x, a0.y), pk2(a0.z, a0.w),
                                         pk2(a1.x, a1.y), pk2(a1.z, a1.w) };
            float2 b01 = *(const float2*)&Bs[k*96 + tx*6];
            float2 b23 = *(const float2*)&Bs[k*96 + tx*6 + 2];
            float2 b45 = *(const float2*)&Bs[k*96 + tx*6 + 4];
            unsigned long long bsp[6] = { pk2(b01.x, b01.x), pk2(b01.y, b01.y),
                                          pk2(b23.x, b23.x), pk2(b23.y, b23.y),
                                          pk2(b45.x, b45.x), pk2(b45.y, b45.y) };
#pragma unroll
            for (int j = 0; j < 6; j++)
#pragma unroll
                for (int r = 0; r < 4; r++)
                    fma2(acc[r][j], ap[r], bsp[j]);
        }
    }

    // epilogue: unpack pairs (rows 2r, 2r+1 within this thread's 8-row block)
#pragma unroll
    for (int r = 0; r < 4; r++) {
#pragma unroll
        for (int j = 0; j < 6; j++) {
            float lo, hi;
            upk2(acc[r][j], lo, hi);
            int col = tx*6 + j;
            int row = m0 + ty*8 + 2*r;
            float bv = bias[col];
            C[(size_t)row*96 + col]     = lo + bv;
            C[(size_t)(row+1)*96 + col] = hi + bv;
        }
    }
}

// ---------------------------------------------------------------------------
// Launch
// ---------------------------------------------------------------------------
extern "C" void kernel_launch(void* const* d_in, const int* in_sizes, int n_in,
                              void* d_out, int out_size) {
    const float* x    = (const float*)d_in[0];
    const float* dist = (const float*)d_in[1];
    const float* w1   = (const float*)d_in[2];
    const float* b1   = (const float*)d_in[3];
    const float* w2   = (const float*)d_in[4];
    const float* b2   = (const float*)d_in[5];
    float* out = (float*)d_out;

    float *dS, *dW2r, *dWt, *dBeff;
    cudaGetSymbolAddress((void**)&dS,    g_S);
    cudaGetSymbolAddress((void**)&dW2r,  g_w2r);
    cudaGetSymbolAddress((void**)&dWt,   g_Wt);
    cudaGetSymbolAddress((void**)&dBeff, g_beff);

    // theta_max goes after the (M x 96) tensor, if the harness expects it
    int nT = MDIM * ED;
    int nTheta = (out_size > nT) ? (out_size - nT) : 0;

    // 1) reorder w2
    w2r_kernel<<<(20*96*96 + 255)/256, 256>>>(w2, dW2r);
    // 2) fold weights
    weff_kernel<<<KDIM, 96>>>(w1, dW2r, dWt);
    // 3) fold bias + theta_max
    prep_kernel<<<1, 96>>>(b1, b2, dW2r, dBeff, out + nT, nTheta);
    // 4) polar bilinear sampling -> S
    sample_kernel<<<(NB*NRr*NAa)/256, 256>>>(x, dist, dS);
    // 5) folded GEMM -> out
    gemm_kernel<<<MDIM/128, 256>>>(dS, dWt, dBeff, out);
}

// round 3
// speedup vs baseline: 1.7369x; 1.7369x over previous
#include <cuda_runtime.h>
#include <cstdint>

// ---------------------------------------------------------------------------
// Problem constants
// ---------------------------------------------------------------------------
#define NB    32
#define IMGW  224
#define HPIX  (IMGW*IMGW)
#define ED    96
#define KDIM  1200               // 3 * 25 * 16 folded patch size
#define KPAD  1216               // padded to multiple of 32 (zero tail)
#define BK    32                 // K-tile
#define NKT   (KPAD/BK)          // 38
#define MDIM  (NB*16*64)         // 32768 output patches
#define PI_F  3.14159265358979323846f
#define SPAD  36                 // smem row pitch in floats (32 + 4 pad)

// Scratch (device globals; no runtime allocation allowed)
__device__ float g_S[(size_t)MDIM * KPAD];    // sampled, patch-major [M][KPAD]
__device__ float g_w2r[20*96*96];             // w2 reordered [ij][c1][c2]
__device__ float g_Wt[ED*KPAD];               // folded weight TRANSPOSED [c2][KPAD]
__device__ float g_beff[ED];                  // folded bias

__device__ __forceinline__ float to_tf32(float v) {
    float r; asm("cvt.rna.tf32.f32 %0, %1;" : "=f"(r) : "f"(v)); return r;
}

// m16n8k8 tf32 mma (row.col), fp32 accum
__device__ __forceinline__ void mma_tf32(float* c, const float* a, const float* b) {
    asm volatile(
        "mma.sync.aligned.m16n8k8.row.col.f32.tf32.tf32.f32 "
        "{%0,%1,%2,%3}, {%4,%5,%6,%7}, {%8,%9}, {%0,%1,%2,%3};"
        : "+f"(c[0]), "+f"(c[1]), "+f"(c[2]), "+f"(c[3])
        : "r"(__float_as_uint(a[0])), "r"(__float_as_uint(a[1])),
          "r"(__float_as_uint(a[2])), "r"(__float_as_uint(a[3])),
          "r"(__float_as_uint(b[0])), "r"(__float_as_uint(b[1])));
}

// ---------------------------------------------------------------------------
// Prep 1: reorder w2 [c2][c1][i][j] -> w2r [ij][c1][c2]
// ---------------------------------------------------------------------------
__global__ void w2r_kernel(const float* __restrict__ w2, float* __restrict__ w2r) {
    int idx = blockIdx.x * blockDim.x + threadIdx.x;
    if (idx >= 20*96*96) return;
    int ij  = idx / (96*96);
    int rem = idx - ij*96*96;
    int c1  = rem / 96;
    int c2  = rem - c1*96;
    int i = ij >> 2, j = ij & 3;
    w2r[idx] = w2[((c2*96 + c1)*5 + i)*4 + j];
}

// ---------------------------------------------------------------------------
// Prep 2: fold weights -> Wt[c2][KPAD] (transposed, tf32-rounded)
// ---------------------------------------------------------------------------
__global__ void weff_kernel(const float* __restrict__ w1,
                            const float* __restrict__ w2r,
                            float* __restrict__ Wt) {
    int k  = blockIdx.x;        // 0..1199
    int c2 = threadIdx.x;       // 0..95
    int c   = k / 400;
    int rem = k - c*400;
    int r = rem >> 4;
    int a = rem & 15;
    int i = r / 5, p = r - i*5;
    int j = a >> 2, q = a & 3;

    __shared__ float w1col[96];
    w1col[c2] = w1[((c2*3 + c)*5 + p)*4 + q];
    __syncthreads();

    const float* wp = w2r + (i*4 + j)*96*96 + c2;
    float s = 0.f;
#pragma unroll 8
    for (int c1 = 0; c1 < 96; c1++) s += w1col[c1] * wp[c1*96];
    Wt[(size_t)c2*KPAD + k] = to_tf32(s);
}

// ---------------------------------------------------------------------------
// Prep 3: folded bias + theta_max output
// ---------------------------------------------------------------------------
__global__ void prep_kernel(const float* __restrict__ b1, const float* __restrict__ b2,
                            const float* __restrict__ w2r, float* __restrict__ beff,
                            float* __restrict__ outTheta, int nTheta) {
    int c2 = threadIdx.x;   // blockDim = 96
    float s = b2[c2];
    for (int c1 = 0; c1 < 96; c1++) {
        float t = 0.f;
#pragma unroll
        for (int ij = 0; ij < 20; ij++) t += w2r[ij*9216 + c1*96 + c2];
        s += b1[c1] * t;
    }
    beff[c2] = s;
    if (c2 < nTheta) outTheta[c2] = 1.5707963267948966f;   // pi/2
}

// Prep 4: zero K pads (cols 1200..1215) of S and Wt
__global__ void zerotail_kernel(float* __restrict__ S, float* __restrict__ Wt) {
    int i = blockIdx.x * blockDim.x + threadIdx.x;
    if (i < MDIM*16)
        S[(size_t)(i >> 4)*KPAD + 1200 + (i & 15)] = 0.f;
    if (i < 96*16)
        Wt[(size_t)(i >> 4)*KPAD + 1200 + (i & 15)] = 0.f;
}

// ---------------------------------------------------------------------------
// Sampling: polar grid + bilinear gather -> S[M][KPAD], tf32-rounded
// ---------------------------------------------------------------------------
__global__ __launch_bounds__(256) void sample_kernel(const float* __restrict__ x,
                                                     const float* __restrict__ dist,
                                                     float* __restrict__ S) {
    int t = blockIdx.x * blockDim.x + threadIdx.x;   // 32*400*1024 threads
    int ia = t & 1023;
    int ir = (t >> 10) % 400;
    int b  = t / (400*1024);

    const float* dp = dist + b*4;
    float c0 = 0.2f + dp[0], c1 = 0.2f + dp[1];
    float c2 = 0.2f + dp[2], c3 = 0.2f + dp[3];

    const float tm = PI_F * 0.5f;
    float th  = tm * (ir + 0.5f) * (1.0f/400.0f);
    float t2  = th*th;
    float pn  = th * (c0 + t2*(c1 + t2*(c2 + t2*c3)));
    float tm2 = tm*tm;
    float pd  = tm * (c0 + tm2*(c1 + tm2*(c2 + tm2*c3)));
    float r   = pn / pd * (IMGW * 0.5f);

    float phi = 2.0f*PI_F * (ia + 0.5f) * (1.0f/1024.0f);
    float sp, cp;
    __sincosf(phi, &sp, &cp);
    float xc = r*cp, yc = r*sp;

    float gx = (yc * (1.0f/112.0f) + 1.0f) * 0.5f * (IMGW - 1);
    float gy = (xc * (1.0f/112.0f) + 1.0f) * 0.5f * (IMGW - 1);

    float x0f = floorf(gx), y0f = floorf(gy);
    float wx1 = gx - x0f, wx0 = 1.0f - wx1;
    float wy1 = gy - y0f, wy0 = 1.0f - wy1;
    int x0 = min(222, max(0, (int)x0f));
    int y0 = min(222, max(0, (int)y0f));

    float w00 = wx0*wy0, w01 = wx1*wy0, w10 = wx0*wy1, w11 = wx1*wy1;

    const float* base = x + (size_t)b*3*HPIX + y0*IMGW + x0;
    int patch = b*1024 + (ir/25)*64 + (ia >> 4);
    float* so = S + (size_t)patch*KPAD + (ir % 25)*16 + (ia & 15);

#pragma unroll
    for (int ch = 0; ch < 3; ch++) {
        const float* p = base + ch*HPIX;
        float v = w00*__ldg(p)        + w01*__ldg(p + 1)
                + w10*__ldg(p + IMGW) + w11*__ldg(p + IMGW + 1);
        so[ch*400] = to_tf32(v);
    }
}

// ---------------------------------------------------------------------------
// Tensor-core GEMM via mma.sync tf32:
//   C[M][96] = S[M][KPAD] @ Wt[96][KPAD]^T + beff
// Block: BM=128 rows, 256 threads (8 warps: 4 along M x 2 along N).
// Warp tile: 32 (two m16) x 48 (six n8). BK=32, single-buffered smem with
// register prefetch of the next K-tile overlapping the MMA work.
// ---------------------------------------------------------------------------
__global__ __launch_bounds__(256, 2)
void gemm_mma(const float* __restrict__ A, const float* __restrict__ Bw,
              const float* __restrict__ bias, float* __restrict__ C) {
    __shared__ float As[128*SPAD];   // [row][k] pitch 36  (18.4 KB)
    __shared__ float Bs[96*SPAD];    // [n][k]   pitch 36  (13.8 KB)

    int tid = threadIdx.x;
    int wid = tid >> 5, lane = tid & 31;
    int wm = wid & 3;          // warp M group: rows wm*32 .. wm*32+31
    int wn = wid >> 2;         // warp N group: cols wn*48 .. wn*48+47
    int g  = lane >> 2;        // octet row/col within fragment
    int tg = lane & 3;

    int m0 = blockIdx.x * 128;
    const float4* Ag = (const float4*)(A + (size_t)m0 * KPAD);
    const float4* Bg = (const float4*)Bw;

    float acc[2][6][4];
#pragma unroll
    for (int mt = 0; mt < 2; mt++)
#pragma unroll
        for (int nt = 0; nt < 6; nt++)
#pragma unroll
            for (int q = 0; q < 4; q++) acc[mt][nt][q] = 0.f;

    // prologue: load K-tile 0 into registers
    float4 ra[4], rb[3];
#pragma unroll
    for (int i = 0; i < 4; i++) {
        int e = i*256 + tid, r = e >> 3, c = e & 7;
        ra[i] = Ag[(size_t)r*(KPAD/4) + c];
    }
#pragma unroll
    for (int i = 0; i < 3; i++) {
        int e = i*256 + tid, r = e >> 3, c = e & 7;
        rb[i] = Bg[(size_t)r*(KPAD/4) + c];
    }

    for (int kt = 0; kt < NKT; ++kt) {
        __syncthreads();   // previous tile's MMAs done reading smem
#pragma unroll
        for (int i = 0; i < 4; i++) {
            int e = i*256 + tid, r = e >> 3, c = e & 7;
            *(float4*)&As[r*SPAD + c*4] = ra[i];
        }
#pragma unroll
        for (int i = 0; i < 3; i++) {
            int e = i*256 + tid, r = e >> 3, c = e & 7;
            *(float4*)&Bs[r*SPAD + c*4] = rb[i];
        }
        __syncthreads();

        if (kt + 1 < NKT) {   // prefetch next K-tile (overlaps MMAs below)
            int ko = (kt + 1) * 8;
#pragma unroll
            for (int i = 0; i < 4; i++) {
                int e = i*256 + tid, r = e >> 3, c = e & 7;
                ra[i] = Ag[(size_t)r*(KPAD/4) + ko + c];
            }
#pragma unroll
            for (int i = 0; i < 3; i++) {
                int e = i*256 + tid, r = e >> 3, c = e & 7;
                rb[i] = Bg[(size_t)r*(KPAD/4) + ko + c];
            }
        }

#pragma unroll
        for (int ks = 0; ks < 4; ks++) {
            int kb = ks * 8;
            float af[2][4];
#pragma unroll
            for (int mt = 0; mt < 2; mt++) {
                int rbase = wm*32 + mt*16;
                af[mt][0] = As[(rbase + g    )*SPAD + kb + tg    ];
                af[mt][1] = As[(rbase + g + 8)*SPAD + kb + tg    ];
                af[mt][2] = As[(rbase + g    )*SPAD + kb + tg + 4];
                af[mt][3] = As[(rbase + g + 8)*SPAD + kb + tg + 4];
            }
            float bf[6][2];
#pragma unroll
            for (int nt = 0; nt < 6; nt++) {
                int n = wn*48 + nt*8 + g;
                bf[nt][0] = Bs[n*SPAD + kb + tg    ];
                bf[nt][1] = Bs[n*SPAD + kb + tg + 4];
            }
#pragma unroll
            for (int mt = 0; mt < 2; mt++)
#pragma unroll
                for (int nt = 0; nt < 6; nt++)
                    mma_tf32(acc[mt][nt], af[mt], bf[nt]);
        }
    }

    // epilogue: c0=(g,2t) c1=(g,2t+1) c2=(g+8,2t) c3=(g+8,2t+1)
#pragma unroll
    for (int nt = 0; nt < 6; nt++) {
        int col = wn*48 + nt*8 + 2*tg;
        float2 bv = *(const float2*)(bias + col);
#pragma unroll
        for (int mt = 0; mt < 2; mt++) {
            int row = m0 + wm*32 + mt*16 + g;
            float2 v0 = { acc[mt][nt][0] + bv.x, acc[mt][nt][1] + bv.y };
            float2 v1 = { acc[mt][nt][2] + bv.x, acc[mt][nt][3] + bv.y };
            *(float2*)(C + (size_t)row*96 + col)       = v0;
            *(float2*)(C + (size_t)(row + 8)*96 + col) = v1;
        }
    }
}

// ---------------------------------------------------------------------------
// Launch
// ---------------------------------------------------------------------------
extern "C" void kernel_launch(void* const* d_in, const int* in_sizes, int n_in,
                              void* d_out, int out_size) {
    const float* x    = (const float*)d_in[0];
    const float* dist = (const float*)d_in[1];
    const float* w1   = (const float*)d_in[2];
    const float* b1   = (const float*)d_in[3];
    const float* w2   = (const float*)d_in[4];
    const float* b2   = (const float*)d_in[5];
    float* out = (float*)d_out;

    float *dS, *dW2r, *dWt, *dBeff;
    cudaGetSymbolAddress((void**)&dS,    g_S);
    cudaGetSymbolAddress((void**)&dW2r,  g_w2r);
    cudaGetSymbolAddress((void**)&dWt,   g_Wt);
    cudaGetSymbolAddress((void**)&dBeff, g_beff);

    int nT = MDIM * ED;
    int nTheta = (out_size > nT) ? (out_size - nT) : 0;

    w2r_kernel<<<(20*96*96 + 255)/256, 256>>>(w2, dW2r);
    weff_kernel<<<KDIM, 96>>>(w1, dW2r, dWt);
    prep_kernel<<<1, 96>>>(b1, b2, dW2r, dBeff, out + nT, nTheta);
    zerotail_kernel<<<(MDIM*16 + 255)/256, 256>>>(dS, dWt);
    sample_kernel<<<(NB*400*1024)/256, 256>>>(x, dist, dS);
    gemm_mma<<<MDIM/128, 256>>>(dS, dWt, dBeff, out);
}